// round 6
// baseline (speedup 1.0000x reference)
#include <cuda_runtime.h>
#include <cstdint>
#include <math.h>

// Problem constants
#define Bb 4
#define Ss 2048
#define Ee 1024
#define Hh 16
#define Dd 64
#define Mm (Bb*Ss)      // 8192
#define Nn (Hh*Dd)      // 1024

// q scale folded with log2(e): exp(s*0.125) = 2^(s*0.125*log2e)
#define QSCL 0.18033688011112042f

// Scratch (device globals: allocation-free, graph-capture safe)
__device__ float g_q[(size_t)Bb*Hh*Ss*Dd];   // [b,h,s,d], pre-scaled by QSCL
__device__ float g_k[(size_t)Bb*Hh*Ss*Dd];   // [b,h,s,d]
__device__ float g_v[(size_t)Bb*Hh*Ss*Dd];   // [b,h,d,s]  (TRANSPOSED)
__device__ float g_z[(size_t)Bb*Hh*Ss*Dd];   // [b,h,s,d]
// tf32-prerounded operands
__device__ float g_xr[(size_t)Mm*Ee];
__device__ float g_wqr[(size_t)Hh*Ee*Dd];
__device__ float g_wkr[(size_t)Hh*Ee*Dd];
__device__ float g_wvr[(size_t)Hh*Ee*Dd];
__device__ float g_wor[(size_t)Nn*Ee];

// ---------------------------------------------------------------------------
// Helpers
// ---------------------------------------------------------------------------
__device__ __forceinline__ float tf32r(float x) {
    float y; asm("cvt.rna.tf32.f32 %0, %1;" : "=f"(y) : "f"(x)); return y;
}
__device__ __forceinline__ float ex2(float x) {
    float y; asm("ex2.approx.f32 %0, %1;" : "=f"(y) : "f"(x)); return y;
}
__device__ __forceinline__ float4 cvt4(float4 v) {
    v.x = tf32r(v.x); v.y = tf32r(v.y); v.z = tf32r(v.z); v.w = tf32r(v.w);
    return v;
}
__device__ __forceinline__ void mma_tf32(float* d, const uint32_t* a,
                                         const uint32_t* b) {
    asm volatile(
        "mma.sync.aligned.m16n8k8.row.col.f32.tf32.tf32.f32 "
        "{%0,%1,%2,%3}, {%4,%5,%6,%7}, {%8,%9}, {%0,%1,%2,%3};"
        : "+f"(d[0]), "+f"(d[1]), "+f"(d[2]), "+f"(d[3])
        : "r"(a[0]), "r"(a[1]), "r"(a[2]), "r"(a[3]), "r"(b[0]), "r"(b[1]));
}
__device__ __forceinline__ uint32_t smem_u32(const void* p) {
    uint32_t a;
    asm("{ .reg .u64 t; cvta.to.shared.u64 t, %1; cvt.u32.u64 %0, t; }"
        : "=r"(a) : "l"(p));
    return a;
}
__device__ __forceinline__ void cpa(uint32_t dst, const void* src) {
    asm volatile("cp.async.cg.shared.global [%0], [%1], 16;"
                 :: "r"(dst), "l"(src));
}
__device__ __forceinline__ void cp_commit() {
    asm volatile("cp.async.commit_group;");
}
template<int N> __device__ __forceinline__ void cp_wait() {
    asm volatile("cp.async.wait_group %0;" :: "n"(N));
}

// ---------------------------------------------------------------------------
// Pre-round pass
// ---------------------------------------------------------------------------
__global__ __launch_bounds__(256)
void round_copy(const float4* __restrict__ src, float4* __restrict__ dst, int n4)
{
    int i = blockIdx.x * 256 + threadIdx.x;
    if (i < n4) dst[i] = cvt4(src[i]);
}

// ---------------------------------------------------------------------------
// GEMM config: 128x128 tile, KC=32, 8 warps (warp tile 64x32), 3-stage cp.async
// ---------------------------------------------------------------------------
#define KC 32
#define AP 36
#define BP 132
#define ABYTES (128*AP*4)
#define BBYTES (KC*BP*4)
#define STG (ABYTES+BBYTES)
#define GEMM_SMEM (3*STG)

// ---------------------------------------------------------------------------
// Kernel 1: QKV projection
// ---------------------------------------------------------------------------
__global__ __launch_bounds__(256, 2)
void proj_mma(const float* __restrict__ bq, const float* __restrict__ bk,
              const float* __restrict__ bv)
{
    extern __shared__ float sm[];
    const uint32_t sb = smem_u32(sm);
    const int sel = blockIdx.z;
    const float* W    = sel == 0 ? g_wqr : (sel == 1 ? g_wkr : g_wvr);
    const float* bias = sel == 0 ? bq    : (sel == 1 ? bk    : bv);

    const int t = threadIdx.x, lane = t & 31, wid = t >> 5;
    const int q = lane & 3, g = lane >> 2;
    const int wm = (wid & 1) * 64, wn = (wid >> 1) * 32;
    const int n0 = blockIdx.x * 128, m0 = blockIdx.y * 128;

    float acc[4][4][4];
    #pragma unroll
    for (int i = 0; i < 4; i++)
        #pragma unroll
        for (int j = 0; j < 4; j++)
            #pragma unroll
            for (int kk = 0; kk < 4; kk++) acc[i][j][kk] = 0.f;

    auto issue = [&](int k0, int s) {
        const uint32_t Ab = sb + s * STG;
        const uint32_t Bbse = Ab + ABYTES;
        #pragma unroll
        for (int j = 0; j < 4; j++) {
            const int idx = t + 256 * j;
            const int row = idx >> 3, k4 = (idx & 7) * 4;
            cpa(Ab + (row * AP + k4) * 4,
                g_xr + (size_t)(m0 + row) * Ee + k0 + k4);
            const int kk = idx >> 5, n4 = (idx & 31) * 4;
            const int ng = n0 + n4;
            cpa(Bbse + (kk * BP + n4) * 4,
                W + (size_t)(ng >> 6) * (Ee * Dd) + (size_t)(k0 + kk) * Dd + (ng & 63));
        }
        cp_commit();
    };
    auto compute = [&](int s) {
        const uint32_t* A = (const uint32_t*)(sm + s * (STG / 4));
        const uint32_t* B = A + ABYTES / 4;
        #pragma unroll
        for (int ks = 0; ks < 4; ks++) {
            const int ko = ks * 8;
            uint32_t af[4][4];
            #pragma unroll
            for (int mt = 0; mt < 4; mt++) {
                const int r = wm + mt * 16 + g;
                af[mt][0] = A[r * AP + ko + q];
                af[mt][1] = A[(r + 8) * AP + ko + q];
                af[mt][2] = A[r * AP + ko + q + 4];
                af[mt][3] = A[(r + 8) * AP + ko + q + 4];
            }
            #pragma unroll
            for (int nt = 0; nt < 4; nt++) {
                const int n = wn + nt * 8 + g;
                uint32_t bf[2];
                bf[0] = B[(ko + q) * BP + n];
                bf[1] = B[(ko + q + 4) * BP + n];
                #pragma unroll
                for (int mt = 0; mt < 4; mt++)
                    mma_tf32(acc[mt][nt], af[mt], bf);
            }
        }
    };

    const int NC = Ee / KC;
    issue(0, 0);
    issue(KC, 1);
    for (int c = 0; c < NC; c++) {
        if (c + 1 < NC) cp_wait<1>(); else cp_wait<0>();
        __syncthreads();
        if (c + 2 < NC) issue((c + 2) * KC, (c + 2) % 3);
        compute(c % 3);
    }

    // Epilogue
    #pragma unroll
    for (int mt = 0; mt < 4; mt++) {
        #pragma unroll
        for (int rr = 0; rr < 2; rr++) {
            const int r_g = m0 + wm + mt * 16 + g + rr * 8;
            const int bi = r_g >> 11, s = r_g & 2047;
            #pragma unroll
            for (int nt = 0; nt < 4; nt++) {
                const int n_g = n0 + wn + nt * 8 + 2 * q;
                const int h = n_g >> 6, d = n_g & 63;
                float vx = acc[mt][nt][2*rr + 0] + bias[n_g];
                float vy = acc[mt][nt][2*rr + 1] + bias[n_g + 1];
                if (sel == 0) {
                    float2 v;
                    v.x = tf32r(vx * QSCL);
                    v.y = tf32r(vy * QSCL);
                    *(float2*)(g_q + ((size_t)(bi * Hh + h) * Ss + s) * Dd + d) = v;
                } else if (sel == 1) {
                    float2 v;
                    v.x = tf32r(vx); v.y = tf32r(vy);
                    *(float2*)(g_k + ((size_t)(bi * Hh + h) * Ss + s) * Dd + d) = v;
                } else {
                    const size_t vb = ((size_t)(bi * Hh + h) * Dd);
                    g_v[(vb + d)     * Ss + s] = tf32r(vx);
                    g_v[(vb + d + 1) * Ss + s] = tf32r(vy);
                }
            }
        }
    }
}

// ---------------------------------------------------------------------------
// Kernel 3: output projection
// ---------------------------------------------------------------------------
__global__ __launch_bounds__(256, 2)
void outproj_mma(const float* __restrict__ bo, float* __restrict__ outp)
{
    extern __shared__ float sm[];
    const uint32_t sb = smem_u32(sm);
    const int t = threadIdx.x, lane = t & 31, wid = t >> 5;
    const int q = lane & 3, g = lane >> 2;
    const int wm = (wid & 1) * 64, wn = (wid >> 1) * 32;
    const int e0 = blockIdx.x * 128, m0 = blockIdx.y * 128;

    float acc[4][4][4];
    #pragma unroll
    for (int i = 0; i < 4; i++)
        #pragma unroll
        for (int j = 0; j < 4; j++)
            #pragma unroll
            for (int kk = 0; kk < 4; kk++) acc[i][j][kk] = 0.f;

    auto issue = [&](int k0, int s) {
        const uint32_t Ab = sb + s * STG;
        const uint32_t Bbse = Ab + ABYTES;
        const int h = k0 >> 6, d0 = k0 & 63;
        #pragma unroll
        for (int j = 0; j < 4; j++) {
            const int idx = t + 256 * j;
            const int row = idx >> 3, k4 = (idx & 7) * 4;
            const int mg = m0 + row, bi = mg >> 11, ss = mg & 2047;
            cpa(Ab + (row * AP + k4) * 4,
                g_z + ((size_t)(bi * Hh + h) * Ss + ss) * Dd + d0 + k4);
            const int kk = idx >> 5, n4 = (idx & 31) * 4;
            cpa(Bbse + (kk * BP + n4) * 4,
                g_wor + (size_t)(k0 + kk) * Ee + e0 + n4);
        }
        cp_commit();
    };
    auto compute = [&](int s) {
        const uint32_t* A = (const uint32_t*)(sm + s * (STG / 4));
        const uint32_t* B = A + ABYTES / 4;
        #pragma unroll
        for (int ks = 0; ks < 4; ks++) {
            const int ko = ks * 8;
            uint32_t af[4][4];
            #pragma unroll
            for (int mt = 0; mt < 4; mt++) {
                const int r = wm + mt * 16 + g;
                af[mt][0] = A[r * AP + ko + q];
                af[mt][1] = A[(r + 8) * AP + ko + q];
                af[mt][2] = A[r * AP + ko + q + 4];
                af[mt][3] = A[(r + 8) * AP + ko + q + 4];
            }
            #pragma unroll
            for (int nt = 0; nt < 4; nt++) {
                const int n = wn + nt * 8 + g;
                uint32_t bf[2];
                bf[0] = B[(ko + q) * BP + n];
                bf[1] = B[(ko + q + 4) * BP + n];
                #pragma unroll
                for (int mt = 0; mt < 4; mt++)
                    mma_tf32(acc[mt][nt], af[mt], bf);
            }
        }
    };

    const int NC = Nn / KC;
    issue(0, 0);
    issue(KC, 1);
    for (int c = 0; c < NC; c++) {
        if (c + 1 < NC) cp_wait<1>(); else cp_wait<0>();
        __syncthreads();
        if (c + 2 < NC) issue((c + 2) * KC, (c + 2) % 3);
        compute(c % 3);
    }

    #pragma unroll
    for (int mt = 0; mt < 4; mt++) {
        #pragma unroll
        for (int rr = 0; rr < 2; rr++) {
            const int r_g = m0 + wm + mt * 16 + g + rr * 8;
            #pragma unroll
            for (int nt = 0; nt < 4; nt++) {
                const int e = e0 + wn + nt * 8 + 2 * q;
                float2 v;
                v.x = acc[mt][nt][2*rr + 0] + bo[e];
                v.y = acc[mt][nt][2*rr + 1] + bo[e + 1];
                *(float2*)(outp + (size_t)r_g * Ee + e) = v;
            }
        }
    }
}

// ---------------------------------------------------------------------------
// Kernel 2: flash attention. 512 threads (16 warps), 256 q-rows/block,
// warp owns 16 rows (1 m16 tile); 64-key tiles, double-buffered K/V.
// Q pre-scaled by 0.125*log2e -> softmax in log2 domain via ex2.
// ---------------------------------------------------------------------------
#define APITCH 68
#define AROWS 256
#define ATHR 512
#define QF (AROWS*APITCH)
#define KVF (64*APITCH)
#define FO_Q  0
#define FO_P  QF
#define FO_K0 (2*QF)
#define FO_V0 (2*QF + KVF)
#define FO_K1 (2*QF + 2*KVF)
#define FO_V1 (2*QF + 3*KVF)
#define ATTN_SMEM ((2*QF + 4*KVF)*4)     // 208896

__global__ __launch_bounds__(ATHR, 1)
void attn_mma()
{
    extern __shared__ float sm[];
    const uint32_t sb = smem_u32(sm);
    const int t = threadIdx.x, lane = t & 31, wid = t >> 5;
    const int q = lane & 3, g = lane >> 2;
    const int bh = blockIdx.y;
    const int row0 = blockIdx.x * AROWS;
    const size_t baseq = (size_t)bh * Ss * Dd;   // q,k: [s][d]
    const size_t basev = (size_t)bh * Dd * Ss;   // v:   [d][s]
    const int wr = wid * 16;                     // warp's 16 rows

    const uint32_t* Qu = (const uint32_t*)sm + FO_Q;
    uint32_t* Pu = (uint32_t*)sm + FO_P;
    float* Ps = sm + FO_P;

    auto issueKV = [&](int t0, int s) {
        const uint32_t Kb = sb + (s ? FO_K1 : FO_K0) * 4;
        const uint32_t Vb = sb + (s ? FO_V1 : FO_V0) * 4;
        #pragma unroll
        for (int j = 0; j < 2; j++) {
            const int idx = t + ATHR * j;
            const int r = idx >> 4, c4 = (idx & 15) * 4;
            cpa(Kb + (r * APITCH + c4) * 4, g_k + baseq + (size_t)(t0 + r) * Dd + c4);
            cpa(Vb + (r * APITCH + c4) * 4, g_v + basev + (size_t)r * Ss + t0 + c4);
        }
        cp_commit();
    };

    // Prologue: Q + KV tile 0, single group
    #pragma unroll
    for (int j = 0; j < 8; j++) {
        const int idx = t + ATHR * j;
        const int r = idx >> 4, c4 = (idx & 15) * 4;
        cpa(sb + (FO_Q + r * APITCH + c4) * 4,
            g_q + baseq + (size_t)(row0 + r) * Dd + c4);
    }
    #pragma unroll
    for (int j = 0; j < 2; j++) {
        const int idx = t + ATHR * j;
        const int r = idx >> 4, c4 = (idx & 15) * 4;
        cpa(sb + (FO_K0 + r * APITCH + c4) * 4, g_k + baseq + (size_t)r * Dd + c4);
        cpa(sb + (FO_V0 + r * APITCH + c4) * 4, g_v + basev + (size_t)r * Ss + c4);
    }
    cp_commit();

    float mR[2], lR[2], o[8][4];
    mR[0] = mR[1] = -3.0e38f; lR[0] = lR[1] = 0.f;
    #pragma unroll
    for (int nt = 0; nt < 8; nt++)
        #pragma unroll
        for (int c = 0; c < 4; c++) o[nt][c] = 0.f;

    const int NT = Ss / 64;
    for (int it = 0; it < NT; it++) {
        cp_wait<0>();
        __syncthreads();
        const int buf = it & 1;
        if (it + 1 < NT) issueKV((it + 1) * 64, buf ^ 1);

        const uint32_t* Ku = (const uint32_t*)sm + (buf ? FO_K1 : FO_K0);
        const uint32_t* Vu = (const uint32_t*)sm + (buf ? FO_V1 : FO_V0);

        // S = Q K^T  (log2-domain scores, scale pre-folded into Q)
        float s[8][4];
        #pragma unroll
        for (int nt = 0; nt < 8; nt++)
            #pragma unroll
            for (int c = 0; c < 4; c++) s[nt][c] = 0.f;
        #pragma unroll
        for (int ks = 0; ks < 8; ks++) {
            const int ko = ks * 8;
            uint32_t af[4];
            af[0] = Qu[(wr + g) * APITCH + ko + q];
            af[1] = Qu[(wr + g + 8) * APITCH + ko + q];
            af[2] = Qu[(wr + g) * APITCH + ko + q + 4];
            af[3] = Qu[(wr + g + 8) * APITCH + ko + q + 4];
            #pragma unroll
            for (int nt = 0; nt < 8; nt++) {
                uint32_t bf[2];
                bf[0] = Ku[(nt * 8 + g) * APITCH + ko + q];
                bf[1] = Ku[(nt * 8 + g) * APITCH + ko + q + 4];
                mma_tf32(s[nt], af, bf);
            }
        }

        // Online softmax (log2 domain). ri=0: row wr+g; ri=1: row wr+8+g.
        #pragma unroll
        for (int rr = 0; rr < 2; rr++) {
            float rmax = -3.0e38f;
            #pragma unroll
            for (int nt = 0; nt < 8; nt++)
                rmax = fmaxf(rmax, fmaxf(s[nt][2*rr], s[nt][2*rr+1]));
            rmax = fmaxf(rmax, __shfl_xor_sync(0xffffffffu, rmax, 1));
            rmax = fmaxf(rmax, __shfl_xor_sync(0xffffffffu, rmax, 2));
            const float mn = fmaxf(mR[rr], rmax);
            float sum = 0.f;
            const int prow = wr + rr * 8 + g;
            #pragma unroll
            for (int nt = 0; nt < 8; nt++) {
                float p0 = ex2(s[nt][2*rr]   - mn);
                float p1 = ex2(s[nt][2*rr+1] - mn);
                sum += p0 + p1;
                float2 v; v.x = tf32r(p0); v.y = tf32r(p1);
                *(float2*)(Ps + prow * APITCH + nt * 8 + 2 * q) = v;
            }
            sum += __shfl_xor_sync(0xffffffffu, sum, 1);
            sum += __shfl_xor_sync(0xffffffffu, sum, 2);
            const float corr = ex2(mR[rr] - mn);
            lR[rr] = lR[rr] * corr + sum;
            mR[rr] = mn;
            #pragma unroll
            for (int nt = 0; nt < 8; nt++) {
                o[nt][2*rr]   *= corr;
                o[nt][2*rr+1] *= corr;
            }
        }
        __syncwarp();

        // O += P V
        #pragma unroll
        for (int ks = 0; ks < 8; ks++) {
            const int ko = ks * 8;
            uint32_t af[4];
            af[0] = Pu[(wr + g) * APITCH + ko + q];
            af[1] = Pu[(wr + g + 8) * APITCH + ko + q];
            af[2] = Pu[(wr + g) * APITCH + ko + q + 4];
            af[3] = Pu[(wr + g + 8) * APITCH + ko + q + 4];
            #pragma unroll
            for (int nt = 0; nt < 8; nt++) {
                uint32_t bf[2];
                bf[0] = Vu[(nt * 8 + g) * APITCH + ko + q];
                bf[1] = Vu[(nt * 8 + g) * APITCH + ko + q + 4];
                mma_tf32(o[nt], af, bf);
            }
        }
    }

    // Normalize, round, write z [B,H,S,Dh]
    #pragma unroll
    for (int rr = 0; rr < 2; rr++) {
        const float inv = 1.0f / lR[rr];
        const int r_g = row0 + wr + rr * 8 + g;
        #pragma unroll
        for (int nt = 0; nt < 8; nt++) {
            const int d = nt * 8 + 2 * q;
            float2 v;
            v.x = tf32r(o[nt][2*rr]   * inv);
            v.y = tf32r(o[nt][2*rr+1] * inv);
            *(float2*)(g_z + baseq + (size_t)r_g * Dd + d) = v;
        }
    }
}

// ---------------------------------------------------------------------------
extern "C" void kernel_launch(void* const* d_in, const int* in_sizes, int n_in,
                              void* d_out, int out_size)
{
    const float* x  = (const float*)d_in[0];
    const float* Wq = (const float*)d_in[1];
    const float* bq = (const float*)d_in[2];
    const float* Wk = (const float*)d_in[3];
    const float* bk = (const float*)d_in[4];
    const float* Wv = (const float*)d_in[5];
    const float* bv = (const float*)d_in[6];
    const float* Wo = (const float*)d_in[7];
    const float* bo = (const float*)d_in[8];
    float* out = (float*)d_out;

    cudaFuncSetAttribute(proj_mma,
                         cudaFuncAttributeMaxDynamicSharedMemorySize, GEMM_SMEM);
    cudaFuncSetAttribute(outproj_mma,
                         cudaFuncAttributeMaxDynamicSharedMemorySize, GEMM_SMEM);
    cudaFuncSetAttribute(attn_mma,
                         cudaFuncAttributeMaxDynamicSharedMemorySize, ATTN_SMEM);

    float *xr, *wqr, *wkr, *wvr, *wor;
    cudaGetSymbolAddress((void**)&xr,  g_xr);
    cudaGetSymbolAddress((void**)&wqr, g_wqr);
    cudaGetSymbolAddress((void**)&wkr, g_wkr);
    cudaGetSymbolAddress((void**)&wvr, g_wvr);
    cudaGetSymbolAddress((void**)&wor, g_wor);

    const int nx4 = Mm * Ee / 4;
    const int nw4 = Hh * Ee * Dd / 4;
    round_copy<<<(nx4 + 255)/256, 256>>>((const float4*)x,  (float4*)xr,  nx4);
    round_copy<<<(nw4 + 255)/256, 256>>>((const float4*)Wq, (float4*)wqr, nw4);
    round_copy<<<(nw4 + 255)/256, 256>>>((const float4*)Wk, (float4*)wkr, nw4);
    round_copy<<<(nw4 + 255)/256, 256>>>((const float4*)Wv, (float4*)wvr, nw4);
    round_copy<<<(nw4 + 255)/256, 256>>>((const float4*)Wo, (float4*)wor, nw4);

    proj_mma<<<dim3(Nn/128, Mm/128, 3), 256, GEMM_SMEM>>>(bq, bk, bv);
    attn_mma<<<dim3(Ss/AROWS, Bb*Hh), ATHR, ATTN_SMEM>>>();
    outproj_mma<<<dim3(Ee/128, Mm/128), 256, GEMM_SMEM>>>(bo, out);
}